// round 6
// baseline (speedup 1.0000x reference)
#include <cuda_runtime.h>
#include <cuda_bf16.h>
#include <cstdint>

#define N_NODES 100000
#define N_EDGES 1600000
#define FDIM    128
#define HEADS   8
#define EPS_F   1e-12f
#define ALPHA_F 0.2f

#define TILE_NODES 64   // nodes per block tile in scores_kernel

// Static device scratch (no runtime allocation).
// g_sc[n*16 + h]  : h<8 -> s_src[n][h], h>=8 -> s_dst[n][h-8]   (6.4 MB, L2-resident)
// g_ssum[n*8 + h] : per-(node,head) sum of exp(e); inverted in place by inv_kernel
__device__ __align__(16) float g_sc[N_NODES * 16];
__device__ __align__(16) float g_ssum[N_NODES * 8];

// ---------------------------------------------------------------------------
// Kernel 1: per-node scores with ZERO inter-thread reduction.
// Block stages 64 x-rows into smem; thread t owns head-row h = t&15 of aa
// (64 registers, loaded once per block) and computes complete 128-length dot
// products for 4 nodes (node-local = (t>>4) + 16k) from smem. Half-warps read
// one broadcast address each -> conflict-free LDS. g_sc stores coalesce to
// 128B per warp. Also zero-initializes g_ssum for the tile.
// ---------------------------------------------------------------------------
__global__ void __launch_bounds__(256) scores_kernel(
    const float* __restrict__ x,
    const float* __restrict__ aa,
    int n_nodes)
{
    __shared__ float4 sx[TILE_NODES * 32];   // 64 rows x 128 floats = 32 KB

    const int t = threadIdx.x;
    const int h = t & 15;          // output row: h<8 -> a_src[h], else a_dst[h-8]
    const int nl0 = t >> 4;        // first local node (0..15)

    // aa half-row for this thread's h, 32 float4 = 64 regs.
    const float4* aa4 = reinterpret_cast<const float4*>(aa);
    float4 areg[32];
    {
        const int base = (h < HEADS) ? (h * 64) : ((h - HEADS) * 64 + 32);
#pragma unroll
        for (int i = 0; i < 32; i++)
            areg[i] = __ldg(&aa4[base + i]);
    }

    const float4* x4 = reinterpret_cast<const float4*>(x);
    const int n_f4 = n_nodes * 32;

    for (int tile = blockIdx.x * TILE_NODES; tile < n_nodes;
         tile += gridDim.x * TILE_NODES) {

        // Stage 64 node rows (2048 float4) coalesced.
        const int base_f4 = tile * 32;
#pragma unroll
        for (int j = 0; j < 8; j++) {
            int idx = t + j * 256;
            int g = base_f4 + idx;
            if (g < n_f4) sx[idx] = x4[g];
        }
        // Zero g_ssum for this tile (64 nodes * 8 floats = 128 float4).
        if (t < 128) {
            int f = tile * 2 + t;                 // float4 index into g_ssum
            if (f < n_nodes * 2)
                reinterpret_cast<float4*>(g_ssum)[f] = make_float4(0.f, 0.f, 0.f, 0.f);
        }
        __syncthreads();

        // 4 outputs per thread: nodes nl0, nl0+16, nl0+32, nl0+48.
#pragma unroll
        for (int k = 0; k < 4; k++) {
            const int nl = nl0 + 16 * k;
            const int node = tile + nl;
            if (node < n_nodes) {
                const float4* xr = &sx[nl * 32];
                float acc = 0.f;
#pragma unroll
                for (int i = 0; i < 32; i++) {
                    float4 xv = xr[i];
                    acc += xv.x * areg[i].x + xv.y * areg[i].y
                         + xv.z * areg[i].z + xv.w * areg[i].w;
                }
                g_sc[(size_t)node * 16 + h] = acc;
            }
        }
        __syncthreads();  // protect sx before next tile's staging
    }
}

// ---------------------------------------------------------------------------
// Half-edge exp: thread handles heads [4h, 4h+4) of edge e. Lane pairs load
// adjacent 16B -> one line per endpoint per edge.
// ---------------------------------------------------------------------------
__device__ __forceinline__ float4 half_edge_exp(int r, int c, int h)
{
    const float4* sc4 = reinterpret_cast<const float4*>(g_sc);
    float4 a = __ldg(&sc4[(size_t)r * 4 + h]);        // src heads 4h..4h+3
    float4 b = __ldg(&sc4[(size_t)c * 4 + 2 + h]);    // dst heads 4h..4h+3

    float ex = a.x + b.x, ey = a.y + b.y, ez = a.z + b.z, ew = a.w + b.w;
    ex = fmaxf(ex, ALPHA_F * ex); ey = fmaxf(ey, ALPHA_F * ey);
    ez = fmaxf(ez, ALPHA_F * ez); ew = fmaxf(ew, ALPHA_F * ew);
    return make_float4(__expf(ex), __expf(ey), __expf(ez), __expf(ew));
}

// ---------------------------------------------------------------------------
// Kernel 2: segment-sum of exp(e). Two threads per edge, one red.v4 each.
// ---------------------------------------------------------------------------
__global__ void __launch_bounds__(256) sum_kernel(
    const int* __restrict__ row,
    const int* __restrict__ col,
    int n_edges)
{
    int t = blockIdx.x * blockDim.x + threadIdx.x;
    int e = t >> 1;
    int h = t & 1;
    if (e >= n_edges) return;
    int r = __ldg(row + e);
    int c = __ldg(col + e);

    float4 exv = half_edge_exp(r, c, h);

    float* dst = g_ssum + (size_t)r * 8 + 4 * h;
    asm volatile("red.global.add.v4.f32 [%0], {%1,%2,%3,%4};"
                 :: "l"(dst), "f"(exv.x), "f"(exv.y), "f"(exv.z), "f"(exv.w)
                 : "memory");
}

// ---------------------------------------------------------------------------
// Kernel 2.5: invert sums in place: g_ssum = 1/(g_ssum + EPS).
// ---------------------------------------------------------------------------
__global__ void __launch_bounds__(256) inv_kernel(int n4)  // n4 = N_NODES*8/4
{
    int i = blockIdx.x * blockDim.x + threadIdx.x;
    if (i >= n4) return;
    float4* p = reinterpret_cast<float4*>(g_ssum);
    float4 v = p[i];
    v.x = __frcp_rn(v.x + EPS_F);
    v.y = __frcp_rn(v.y + EPS_F);
    v.z = __frcp_rn(v.z + EPS_F);
    v.w = __frcp_rn(v.w + EPS_F);
    p[i] = v;
}

// ---------------------------------------------------------------------------
// Kernel 3: a[head][e] = exp * inv_ssum[r][head]. Two threads per edge.
// ---------------------------------------------------------------------------
__global__ void __launch_bounds__(256) out_kernel(
    const int* __restrict__ row,
    const int* __restrict__ col,
    float* __restrict__ out,
    int n_edges)
{
    int t = blockIdx.x * blockDim.x + threadIdx.x;
    int e = t >> 1;
    int h = t & 1;
    if (e >= n_edges) return;
    int r = __ldg(row + e);
    int c = __ldg(col + e);

    float4 exv = half_edge_exp(r, c, h);

    const float4* ss4 = reinterpret_cast<const float4*>(g_ssum);
    float4 s = __ldg(&ss4[(size_t)r * 2 + h]);

    size_t E = (size_t)n_edges;
    float* o = out + (size_t)(4 * h) * E + e;
    o[0 * E] = exv.x * s.x;
    o[1 * E] = exv.y * s.y;
    o[2 * E] = exv.z * s.z;
    o[3 * E] = exv.w * s.w;
}

extern "C" void kernel_launch(void* const* d_in, const int* in_sizes, int n_in,
                              void* d_out, int out_size)
{
    const float* x   = (const float*)d_in[0];
    const int*   row = (const int*)  d_in[1];
    const int*   col = (const int*)  d_in[2];
    const float* aa  = (const float*)d_in[3];
    float* out = (float*)d_out;

    int n_nodes = in_sizes[0] / FDIM;   // 100000
    int n_edges = in_sizes[1];          // 1600000

    scores_kernel<<<296, 256>>>(x, aa, n_nodes);

    int nthreads = 2 * n_edges;
    sum_kernel<<<(nthreads + 255) / 256, 256>>>(row, col, n_edges);
    {
        int n4 = n_nodes * HEADS / 4;
        inv_kernel<<<(n4 + 255) / 256, 256>>>(n4);
    }
    out_kernel<<<(nthreads + 255) / 256, 256>>>(row, col, out, n_edges);
}

// round 7
// speedup vs baseline: 1.0289x; 1.0289x over previous
#include <cuda_runtime.h>
#include <cuda_bf16.h>
#include <cstdint>

#define N_NODES 100000
#define N_EDGES 1600000
#define FDIM    128
#define HEADS   8
#define EPS_F   1e-12f
#define ALPHA_F 0.2f

// Static device scratch (no runtime allocation).
// g_srcsum[n*16 + j] : j<8 -> s_src[n][j] ; j>=8 -> ssum[n][j-8] (accumulated,
//                      then inverted in place). One 64B row per node, so an
//                      edge's src-score gather and ssum gather share a line.
// g_dst[n*8 + j]     : s_dst[n][j] (32B row).
__device__ __align__(128) float g_srcsum[N_NODES * 16];
__device__ __align__(128) float g_dst[N_NODES * 8];

// ---------------------------------------------------------------------------
// Kernel 1: per-node scores. One warp per node (grid-stride loop). R5 variant:
// aa in 64 regs/lane; value-splitting reduction with compile-time register
// indices; 16 SHFL per node. Even lanes write scores (src -> g_srcsum,
// dst -> g_dst); odd lanes zero the ssum half of g_srcsum.
// ---------------------------------------------------------------------------
__global__ void __launch_bounds__(256) scores_kernel(
    const float* __restrict__ x,
    const float* __restrict__ aa,
    int n_nodes)
{
    const int lane  = threadIdx.x & 31;
    const int gwarp = (blockIdx.x * blockDim.x + threadIdx.x) >> 5;
    const int nwarp = (gridDim.x * blockDim.x) >> 5;

    float4 areg[16];
    const float4* aa4 = reinterpret_cast<const float4*>(aa);
#pragma unroll
    for (int h = 0; h < HEADS; h++) {
        areg[h]         = __ldg(&aa4[h * 64 + lane]);        // a_src[h]
        areg[HEADS + h] = __ldg(&aa4[h * 64 + 32 + lane]);   // a_dst[h]
    }

    const bool b16 = (lane & 16) != 0;
    const bool b8  = (lane & 8)  != 0;
    const bool b4  = (lane & 4)  != 0;
    const bool b2  = (lane & 2)  != 0;

    const float4* x4 = reinterpret_cast<const float4*>(x);

    for (int node = gwarp; node < n_nodes; node += nwarp) {
        float4 xv = __ldg(&x4[(size_t)node * 32 + lane]);

        float acc[16];
#pragma unroll
        for (int i = 0; i < 16; i++)
            acc[i] = xv.x * areg[i].x + xv.y * areg[i].y
                   + xv.z * areg[i].z + xv.w * areg[i].w;

#pragma unroll
        for (int i = 0; i < 8; i++) {
            float give = b16 ? acc[i]     : acc[i + 8];
            float keep = b16 ? acc[i + 8] : acc[i];
            acc[i] = keep + __shfl_xor_sync(0xffffffffu, give, 16);
        }
#pragma unroll
        for (int i = 0; i < 4; i++) {
            float give = b8 ? acc[i]     : acc[i + 4];
            float keep = b8 ? acc[i + 4] : acc[i];
            acc[i] = keep + __shfl_xor_sync(0xffffffffu, give, 8);
        }
#pragma unroll
        for (int i = 0; i < 2; i++) {
            float give = b4 ? acc[i]     : acc[i + 2];
            float keep = b4 ? acc[i + 2] : acc[i];
            acc[i] = keep + __shfl_xor_sync(0xffffffffu, give, 4);
        }
        {
            float give = b2 ? acc[0] : acc[1];
            float keep = b2 ? acc[1] : acc[0];
            acc[0] = keep + __shfl_xor_sync(0xffffffffu, give, 2);
        }
        // lanes 2v, 2v+1 hold value v (v<8: src head v; v>=8: dst head v-8)
        float r = acc[0] + __shfl_xor_sync(0xffffffffu, acc[0], 1);
        int v = lane >> 1;

        if (!(lane & 1)) {
            if (v < HEADS) g_srcsum[(size_t)node * 16 + v] = r;
            else           g_dst[(size_t)node * 8 + (v - HEADS)] = r;
        } else if (v < HEADS) {
            g_srcsum[(size_t)node * 16 + 8 + v] = 0.0f;   // init ssum half
        }
    }
}

// ---------------------------------------------------------------------------
// Half-edge exp: thread handles heads [4h, 4h+4) of edge e (h in {0,1}).
// Edge pair coalesces: src reads 32B contiguous of r's 64B row, dst reads
// 32B contiguous of c's 32B row -> 1 line each.
// ---------------------------------------------------------------------------
__device__ __forceinline__ float4 half_edge_exp(int r, int c, int h)
{
    const float4* s4 = reinterpret_cast<const float4*>(g_srcsum);
    const float4* d4 = reinterpret_cast<const float4*>(g_dst);
    float4 a = __ldg(&s4[(size_t)r * 4 + h]);     // src heads 4h..4h+3
    float4 b = __ldg(&d4[(size_t)c * 2 + h]);     // dst heads 4h..4h+3

    float ex = a.x + b.x, ey = a.y + b.y, ez = a.z + b.z, ew = a.w + b.w;
    ex = fmaxf(ex, ALPHA_F * ex); ey = fmaxf(ey, ALPHA_F * ey);
    ez = fmaxf(ez, ALPHA_F * ez); ew = fmaxf(ew, ALPHA_F * ew);
    return make_float4(__expf(ex), __expf(ey), __expf(ez), __expf(ew));
}

// ---------------------------------------------------------------------------
// Kernel 2: segment-sum of exp(e). Two threads per edge, one red.v4 each,
// accumulating into the ssum half of the src node's row.
// ---------------------------------------------------------------------------
__global__ void __launch_bounds__(256) sum_kernel(
    const int* __restrict__ row,
    const int* __restrict__ col,
    int n_edges)
{
    int t = blockIdx.x * blockDim.x + threadIdx.x;
    int e = t >> 1;
    int h = t & 1;
    if (e >= n_edges) return;
    int r = __ldg(row + e);
    int c = __ldg(col + e);

    float4 exv = half_edge_exp(r, c, h);

    float* dst = g_srcsum + (size_t)r * 16 + 8 + 4 * h;
    asm volatile("red.global.add.v4.f32 [%0], {%1,%2,%3,%4};"
                 :: "l"(dst), "f"(exv.x), "f"(exv.y), "f"(exv.z), "f"(exv.w)
                 : "memory");
}

// ---------------------------------------------------------------------------
// Kernel 2.5: invert the ssum half of each row: s := 1/(s + EPS).
// i indexes the 2*N_NODES float4 ssum slots.
// ---------------------------------------------------------------------------
__global__ void __launch_bounds__(256) inv_kernel(int n2)  // n2 = N_NODES*2
{
    int i = blockIdx.x * blockDim.x + threadIdx.x;
    if (i >= n2) return;
    float4* p = reinterpret_cast<float4*>(g_srcsum) + ((size_t)(i >> 1) * 4 + 2 + (i & 1));
    float4 v = *p;
    v.x = __frcp_rn(v.x + EPS_F);
    v.y = __frcp_rn(v.y + EPS_F);
    v.z = __frcp_rn(v.z + EPS_F);
    v.w = __frcp_rn(v.w + EPS_F);
    *p = v;
}

// ---------------------------------------------------------------------------
// Kernel 3: a[head][e] = exp * inv_ssum[r][head]. Two threads per edge.
// r-row gathers (src 16B + inv_ssum 16B per thread; 64B per pair) hit ONE
// line; dst hits one line -> 2 scattered wavefronts per edge (was 3).
// ---------------------------------------------------------------------------
__global__ void __launch_bounds__(256) out_kernel(
    const int* __restrict__ row,
    const int* __restrict__ col,
    float* __restrict__ out,
    int n_edges)
{
    int t = blockIdx.x * blockDim.x + threadIdx.x;
    int e = t >> 1;
    int h = t & 1;
    if (e >= n_edges) return;
    int r = __ldg(row + e);
    int c = __ldg(col + e);

    const float4* s4 = reinterpret_cast<const float4*>(g_srcsum);
    const float4* d4 = reinterpret_cast<const float4*>(g_dst);
    float4 a = __ldg(&s4[(size_t)r * 4 + h]);          // src scores
    float4 s = __ldg(&s4[(size_t)r * 4 + 2 + h]);      // inv ssum (same line)
    float4 b = __ldg(&d4[(size_t)c * 2 + h]);          // dst scores

    float e0 = a.x + b.x, e1 = a.y + b.y, e2 = a.z + b.z, e3 = a.w + b.w;
    e0 = fmaxf(e0, ALPHA_F * e0); e1 = fmaxf(e1, ALPHA_F * e1);
    e2 = fmaxf(e2, ALPHA_F * e2); e3 = fmaxf(e3, ALPHA_F * e3);

    size_t E = (size_t)n_edges;
    float* o = out + (size_t)(4 * h) * E + e;
    o[0 * E] = __expf(e0) * s.x;
    o[1 * E] = __expf(e1) * s.y;
    o[2 * E] = __expf(e2) * s.z;
    o[3 * E] = __expf(e3) * s.w;
}

extern "C" void kernel_launch(void* const* d_in, const int* in_sizes, int n_in,
                              void* d_out, int out_size)
{
    const float* x   = (const float*)d_in[0];
    const int*   row = (const int*)  d_in[1];
    const int*   col = (const int*)  d_in[2];
    const float* aa  = (const float*)d_in[3];
    float* out = (float*)d_out;

    int n_nodes = in_sizes[0] / FDIM;   // 100000
    int n_edges = in_sizes[1];          // 1600000

    scores_kernel<<<1184, 256>>>(x, aa, n_nodes);

    int nthreads = 2 * n_edges;
    sum_kernel<<<(nthreads + 255) / 256, 256>>>(row, col, n_edges);
    {
        int n2 = n_nodes * 2;
        inv_kernel<<<(n2 + 255) / 256, 256>>>(n2);
    }
    out_kernel<<<(nthreads + 255) / 256, 256>>>(row, col, out, n_edges);
}

// round 8
// speedup vs baseline: 1.0673x; 1.0373x over previous
#include <cuda_runtime.h>
#include <cuda_bf16.h>
#include <cstdint>

#define N_NODES 100000
#define N_EDGES 1600000
#define FDIM    128
#define HEADS   8
#define EPS_F   1e-12f
#define ALPHA_F 0.2f

// Static device scratch (no runtime allocation).
// g_srcsum[n*16 + j] : j<8 -> s_src[n][j] ; j>=8 -> ssum[n][j-8] (accumulated,
//                      then inverted in place). 64B row per node: an edge's
//                      src-score gather and ssum gather share one line.
// g_dst[n*8 + j]     : s_dst[n][j] (32B row).
__device__ __align__(128) float g_srcsum[N_NODES * 16];
__device__ __align__(128) float g_dst[N_NODES * 8];

// ---------------------------------------------------------------------------
// Kernel 1: per-node scores, TWO warps per node (role 0 = src rows, role 1 =
// dst rows). areg is 8 rows x float4 = 32 regs (vs 64 for 16 rows) -> ~60
// regs/thread -> 4 blocks/SM = 32 warps/SM (2x the old occupancy).
// Value-splitting reduction over 8 values: 9 SHFL/warp, compile-time indices.
// After reduction, all 4 lanes of group (lane>>2) hold the full sum of value
// v = (lane>>2)&7; lane with (lane&3)==0 writes it; (lane&3)==1 on the src
// warp zeroes the ssum slot.
// ---------------------------------------------------------------------------
__global__ void __launch_bounds__(256) scores_kernel(
    const float* __restrict__ x,
    const float* __restrict__ aa,
    int n_nodes)
{
    const int lane  = threadIdx.x & 31;
    const int gwarp = (blockIdx.x * blockDim.x + threadIdx.x) >> 5;
    const int nwarp = (gridDim.x * blockDim.x) >> 5;
    const int role  = gwarp & 1;            // 0: src rows, 1: dst rows
    const int wnode0 = gwarp >> 1;          // first node for this warp
    const int nstep  = nwarp >> 1;          // node stride

    // areg[i] = aa row i (src half if role 0, dst half if role 1),
    // features [4*lane, 4*lane+4). 8 float4 = 32 regs.
    float4 areg[8];
    const float4* aa4 = reinterpret_cast<const float4*>(aa);
    {
        const int off = role ? 32 : 0;
#pragma unroll
        for (int i = 0; i < 8; i++)
            areg[i] = __ldg(&aa4[i * 64 + off + lane]);
    }

    const bool b16 = (lane & 16) != 0;
    const bool b8  = (lane & 8)  != 0;
    const bool b4  = (lane & 4)  != 0;
    const int  v   = (lane >> 2) & 7;       // value index this lane ends with
    const int  sub = lane & 3;              // sub-lane within value group

    const float4* x4 = reinterpret_cast<const float4*>(x);

    for (int node = wnode0; node < n_nodes; node += nstep) {
        float4 xv = __ldg(&x4[(size_t)node * 32 + lane]);

        float acc[8];
#pragma unroll
        for (int i = 0; i < 8; i++)
            acc[i] = xv.x * areg[i].x + xv.y * areg[i].y
                   + xv.z * areg[i].z + xv.w * areg[i].w;

        // Round 1 (xor 16): 8 -> 4 values. Hi half keeps rows 4..7.
#pragma unroll
        for (int i = 0; i < 4; i++) {
            float give = b16 ? acc[i]     : acc[i + 4];
            float keep = b16 ? acc[i + 4] : acc[i];
            acc[i] = keep + __shfl_xor_sync(0xffffffffu, give, 16);
        }
        // Round 2 (xor 8): 4 -> 2.
#pragma unroll
        for (int i = 0; i < 2; i++) {
            float give = b8 ? acc[i]     : acc[i + 2];
            float keep = b8 ? acc[i + 2] : acc[i];
            acc[i] = keep + __shfl_xor_sync(0xffffffffu, give, 8);
        }
        // Round 3 (xor 4): 2 -> 1.
        {
            float give = b4 ? acc[0] : acc[1];
            float keep = b4 ? acc[1] : acc[0];
            acc[0] = keep + __shfl_xor_sync(0xffffffffu, give, 4);
        }
        // Rounds 4-5: sum the 4 sub-lanes of each value group.
        acc[0] += __shfl_xor_sync(0xffffffffu, acc[0], 2);
        acc[0] += __shfl_xor_sync(0xffffffffu, acc[0], 1);
        // All 4 lanes of group now hold the full dot for value v.

        if (role == 0) {
            if (sub == 0)      g_srcsum[(size_t)node * 16 + v]     = acc[0];
            else if (sub == 1) g_srcsum[(size_t)node * 16 + 8 + v] = 0.0f;
        } else {
            if (sub == 0)      g_dst[(size_t)node * 8 + v] = acc[0];
        }
    }
}

// ---------------------------------------------------------------------------
// Kernel 2: segment-sum of exp(e). Two threads per edge, one red.v4 each,
// accumulating into the ssum half of the src node's row.
// ---------------------------------------------------------------------------
__global__ void __launch_bounds__(256) sum_kernel(
    const int* __restrict__ row,
    const int* __restrict__ col,
    int n_edges)
{
    int t = blockIdx.x * blockDim.x + threadIdx.x;
    int e = t >> 1;
    int h = t & 1;
    if (e >= n_edges) return;
    int r = __ldg(row + e);
    int c = __ldg(col + e);

    const float4* s4 = reinterpret_cast<const float4*>(g_srcsum);
    const float4* d4 = reinterpret_cast<const float4*>(g_dst);
    float4 a = __ldg(&s4[(size_t)r * 4 + h]);     // src heads 4h..4h+3
    float4 b = __ldg(&d4[(size_t)c * 2 + h]);     // dst heads 4h..4h+3

    float e0 = a.x + b.x, e1 = a.y + b.y, e2 = a.z + b.z, e3 = a.w + b.w;
    e0 = fmaxf(e0, ALPHA_F * e0); e1 = fmaxf(e1, ALPHA_F * e1);
    e2 = fmaxf(e2, ALPHA_F * e2); e3 = fmaxf(e3, ALPHA_F * e3);

    float x0 = __expf(e0), x1 = __expf(e1), x2 = __expf(e2), x3 = __expf(e3);

    float* dst = g_srcsum + (size_t)r * 16 + 8 + 4 * h;
    asm volatile("red.global.add.v4.f32 [%0], {%1,%2,%3,%4};"
                 :: "l"(dst), "f"(x0), "f"(x1), "f"(x2), "f"(x3)
                 : "memory");
}

// ---------------------------------------------------------------------------
// Kernel 2.5: invert the ssum half of each row: s := 1/(s + EPS).
// ---------------------------------------------------------------------------
__global__ void __launch_bounds__(256) inv_kernel(int n2)  // n2 = N_NODES*2
{
    int i = blockIdx.x * blockDim.x + threadIdx.x;
    if (i >= n2) return;
    float4* p = reinterpret_cast<float4*>(g_srcsum) + ((size_t)(i >> 1) * 4 + 2 + (i & 1));
    float4 v = *p;
    v.x = __frcp_rn(v.x + EPS_F);
    v.y = __frcp_rn(v.y + EPS_F);
    v.z = __frcp_rn(v.z + EPS_F);
    v.w = __frcp_rn(v.w + EPS_F);
    *p = v;
}

// ---------------------------------------------------------------------------
// Kernel 3: a[head][e] = exp * inv_ssum[r][head]. Two threads per edge.
// src scores + inv ssum share one 64B row (one line per edge pair).
// ---------------------------------------------------------------------------
__global__ void __launch_bounds__(256) out_kernel(
    const int* __restrict__ row,
    const int* __restrict__ col,
    float* __restrict__ out,
    int n_edges)
{
    int t = blockIdx.x * blockDim.x + threadIdx.x;
    int e = t >> 1;
    int h = t & 1;
    if (e >= n_edges) return;
    int r = __ldg(row + e);
    int c = __ldg(col + e);

    const float4* s4 = reinterpret_cast<const float4*>(g_srcsum);
    const float4* d4 = reinterpret_cast<const float4*>(g_dst);
    float4 a = __ldg(&s4[(size_t)r * 4 + h]);          // src scores
    float4 s = __ldg(&s4[(size_t)r * 4 + 2 + h]);      // inv ssum (same line)
    float4 b = __ldg(&d4[(size_t)c * 2 + h]);          // dst scores

    float e0 = a.x + b.x, e1 = a.y + b.y, e2 = a.z + b.z, e3 = a.w + b.w;
    e0 = fmaxf(e0, ALPHA_F * e0); e1 = fmaxf(e1, ALPHA_F * e1);
    e2 = fmaxf(e2, ALPHA_F * e2); e3 = fmaxf(e3, ALPHA_F * e3);

    size_t E = (size_t)n_edges;
    float* o = out + (size_t)(4 * h) * E + e;
    o[0 * E] = __expf(e0) * s.x;
    o[1 * E] = __expf(e1) * s.y;
    o[2 * E] = __expf(e2) * s.z;
    o[3 * E] = __expf(e3) * s.w;
}

extern "C" void kernel_launch(void* const* d_in, const int* in_sizes, int n_in,
                              void* d_out, int out_size)
{
    const float* x   = (const float*)d_in[0];
    const int*   row = (const int*)  d_in[1];
    const int*   col = (const int*)  d_in[2];
    const float* aa  = (const float*)d_in[3];
    float* out = (float*)d_out;

    int n_nodes = in_sizes[0] / FDIM;   // 100000
    int n_edges = in_sizes[1];          // 1600000

    // 592 blocks = 4/SM co-resident; 4736 warps = 2368 node-pairs in flight.
    scores_kernel<<<592, 256>>>(x, aa, n_nodes);

    int nthreads = 2 * n_edges;
    sum_kernel<<<(nthreads + 255) / 256, 256>>>(row, col, n_edges);
    {
        int n2 = n_nodes * 2;
        inv_kernel<<<(n2 + 255) / 256, 256>>>(n2);
    }
    out_kernel<<<(nthreads + 255) / 256, 256>>>(row, col, out, n_edges);
}

// round 9
// speedup vs baseline: 1.1213x; 1.0507x over previous
#include <cuda_runtime.h>
#include <cuda_bf16.h>
#include <cstdint>

#define N_NODES 100000
#define N_EDGES 1600000
#define FDIM    128
#define HEADS   8
#define EPS_F   1e-12f
#define ALPHA_F 0.2f

// Static device scratch (no runtime allocation).
// g_srcsum[n*16 + j] : j<8 -> s_src[n][j] ; j>=8 -> ssum[n][j-8] (accumulated,
//                      then inverted in place). 64B row per node: an edge's
//                      src-score gather and ssum gather share one line.
// g_dst[n*8 + j]     : s_dst[n][j] (32B row).
__device__ __align__(128) float g_srcsum[N_NODES * 16];
__device__ __align__(128) float g_dst[N_NODES * 8];

// ---------------------------------------------------------------------------
// Kernel 1: per-node scores, TWO warps per node-pair role split (role 0 = src
// rows, role 1 = dst rows) AND two nodes per loop iteration: both x-row loads
// issue before either reduction consumes them (MLP 2/warp vs 1).
// areg: 8 float4 = 32 regs. Value-splitting reduction, compile-time indices,
// 9 SHFL per node.
// ---------------------------------------------------------------------------
__global__ void __launch_bounds__(256) scores_kernel(
    const float* __restrict__ x,
    const float* __restrict__ aa,
    int n_nodes)
{
    const int lane  = threadIdx.x & 31;
    const int gwarp = (blockIdx.x * blockDim.x + threadIdx.x) >> 5;
    const int nwarp = (gridDim.x * blockDim.x) >> 5;
    const int role  = gwarp & 1;            // 0: src rows, 1: dst rows
    const int wnode0 = gwarp >> 1;          // first node for this warp
    const int nstep  = nwarp >> 1;          // node stride

    float4 areg[8];
    const float4* aa4 = reinterpret_cast<const float4*>(aa);
    {
        const int off = role ? 32 : 0;
#pragma unroll
        for (int i = 0; i < 8; i++)
            areg[i] = __ldg(&aa4[i * 64 + off + lane]);
    }

    const bool b16 = (lane & 16) != 0;
    const bool b8  = (lane & 8)  != 0;
    const bool b4  = (lane & 4)  != 0;
    const int  v   = (lane >> 2) & 7;       // value index this lane ends with
    const int  sub = lane & 3;              // sub-lane within value group

    const float4* x4 = reinterpret_cast<const float4*>(x);

    for (int node = wnode0; node < n_nodes; node += 2 * nstep) {
        const int nodeB = node + nstep;
        const bool hasB = (nodeB < n_nodes);

        // Issue both independent loads first (MLP=2).
        float4 xvA = __ldg(&x4[(size_t)node * 32 + lane]);
        float4 xvB;
        if (hasB) xvB = __ldg(&x4[(size_t)nodeB * 32 + lane]);

        float accA[8], accB[8];
#pragma unroll
        for (int i = 0; i < 8; i++)
            accA[i] = xvA.x * areg[i].x + xvA.y * areg[i].y
                    + xvA.z * areg[i].z + xvA.w * areg[i].w;
        if (hasB) {
#pragma unroll
            for (int i = 0; i < 8; i++)
                accB[i] = xvB.x * areg[i].x + xvB.y * areg[i].y
                        + xvB.z * areg[i].z + xvB.w * areg[i].w;
        }

        // Interleaved value-splitting reductions (A and B independent).
#pragma unroll
        for (int i = 0; i < 4; i++) {
            float gA = b16 ? accA[i] : accA[i + 4];
            float kA = b16 ? accA[i + 4] : accA[i];
            accA[i] = kA + __shfl_xor_sync(0xffffffffu, gA, 16);
        }
        if (hasB) {
#pragma unroll
            for (int i = 0; i < 4; i++) {
                float gB = b16 ? accB[i] : accB[i + 4];
                float kB = b16 ? accB[i + 4] : accB[i];
                accB[i] = kB + __shfl_xor_sync(0xffffffffu, gB, 16);
            }
        }
#pragma unroll
        for (int i = 0; i < 2; i++) {
            float gA = b8 ? accA[i] : accA[i + 2];
            float kA = b8 ? accA[i + 2] : accA[i];
            accA[i] = kA + __shfl_xor_sync(0xffffffffu, gA, 8);
        }
        if (hasB) {
#pragma unroll
            for (int i = 0; i < 2; i++) {
                float gB = b8 ? accB[i] : accB[i + 2];
                float kB = b8 ? accB[i + 2] : accB[i];
                accB[i] = kB + __shfl_xor_sync(0xffffffffu, gB, 8);
            }
        }
        {
            float gA = b4 ? accA[0] : accA[1];
            float kA = b4 ? accA[1] : accA[0];
            accA[0] = kA + __shfl_xor_sync(0xffffffffu, gA, 4);
        }
        if (hasB) {
            float gB = b4 ? accB[0] : accB[1];
            float kB = b4 ? accB[1] : accB[0];
            accB[0] = kB + __shfl_xor_sync(0xffffffffu, gB, 4);
        }
        accA[0] += __shfl_xor_sync(0xffffffffu, accA[0], 2);
        if (hasB) accB[0] += __shfl_xor_sync(0xffffffffu, accB[0], 2);
        accA[0] += __shfl_xor_sync(0xffffffffu, accA[0], 1);
        if (hasB) accB[0] += __shfl_xor_sync(0xffffffffu, accB[0], 1);

        if (role == 0) {
            if (sub == 0) {
                g_srcsum[(size_t)node * 16 + v] = accA[0];
                if (hasB) g_srcsum[(size_t)nodeB * 16 + v] = accB[0];
            } else if (sub == 1) {
                g_srcsum[(size_t)node * 16 + 8 + v] = 0.0f;
                if (hasB) g_srcsum[(size_t)nodeB * 16 + 8 + v] = 0.0f;
            }
        } else {
            if (sub == 0) {
                g_dst[(size_t)node * 8 + v] = accA[0];
                if (hasB) g_dst[(size_t)nodeB * 8 + v] = accB[0];
            }
        }
    }
}

// ---------------------------------------------------------------------------
// Kernel 2: segment-sum of exp(e). Two threads per edge, one red.v4 each,
// accumulating into the ssum half of the src node's row.
// ---------------------------------------------------------------------------
__global__ void __launch_bounds__(256) sum_kernel(
    const int* __restrict__ row,
    const int* __restrict__ col,
    int n_edges)
{
    int t = blockIdx.x * blockDim.x + threadIdx.x;
    int e = t >> 1;
    int h = t & 1;
    if (e >= n_edges) return;
    int r = __ldg(row + e);
    int c = __ldg(col + e);

    const float4* s4 = reinterpret_cast<const float4*>(g_srcsum);
    const float4* d4 = reinterpret_cast<const float4*>(g_dst);
    float4 a = __ldg(&s4[(size_t)r * 4 + h]);     // src heads 4h..4h+3
    float4 b = __ldg(&d4[(size_t)c * 2 + h]);     // dst heads 4h..4h+3

    float e0 = a.x + b.x, e1 = a.y + b.y, e2 = a.z + b.z, e3 = a.w + b.w;
    e0 = fmaxf(e0, ALPHA_F * e0); e1 = fmaxf(e1, ALPHA_F * e1);
    e2 = fmaxf(e2, ALPHA_F * e2); e3 = fmaxf(e3, ALPHA_F * e3);

    float x0 = __expf(e0), x1 = __expf(e1), x2 = __expf(e2), x3 = __expf(e3);

    float* dst = g_srcsum + (size_t)r * 16 + 8 + 4 * h;
    asm volatile("red.global.add.v4.f32 [%0], {%1,%2,%3,%4};"
                 :: "l"(dst), "f"(x0), "f"(x1), "f"(x2), "f"(x3)
                 : "memory");
}

// ---------------------------------------------------------------------------
// Kernel 2.5: invert the ssum half of each row: s := 1/(s + EPS).
// ---------------------------------------------------------------------------
__global__ void __launch_bounds__(256) inv_kernel(int n2)  // n2 = N_NODES*2
{
    int i = blockIdx.x * blockDim.x + threadIdx.x;
    if (i >= n2) return;
    float4* p = reinterpret_cast<float4*>(g_srcsum) + ((size_t)(i >> 1) * 4 + 2 + (i & 1));
    float4 v = *p;
    v.x = __frcp_rn(v.x + EPS_F);
    v.y = __frcp_rn(v.y + EPS_F);
    v.z = __frcp_rn(v.z + EPS_F);
    v.w = __frcp_rn(v.w + EPS_F);
    *p = v;
}

// ---------------------------------------------------------------------------
// Kernel 3: a[head][e] = exp * inv_ssum[r][head]. Two threads per edge.
// src scores + inv ssum share one 64B row (one line per edge pair).
// ---------------------------------------------------------------------------
__global__ void __launch_bounds__(256) out_kernel(
    const int* __restrict__ row,
    const int* __restrict__ col,
    float* __restrict__ out,
    int n_edges)
{
    int t = blockIdx.x * blockDim.x + threadIdx.x;
    int e = t >> 1;
    int h = t & 1;
    if (e >= n_edges) return;
    int r = __ldg(row + e);
    int c = __ldg(col + e);

    const float4* s4 = reinterpret_cast<const float4*>(g_srcsum);
    const float4* d4 = reinterpret_cast<const float4*>(g_dst);
    float4 a = __ldg(&s4[(size_t)r * 4 + h]);          // src scores
    float4 s = __ldg(&s4[(size_t)r * 4 + 2 + h]);      // inv ssum (same line)
    float4 b = __ldg(&d4[(size_t)c * 2 + h]);          // dst scores

    float e0 = a.x + b.x, e1 = a.y + b.y, e2 = a.z + b.z, e3 = a.w + b.w;
    e0 = fmaxf(e0, ALPHA_F * e0); e1 = fmaxf(e1, ALPHA_F * e1);
    e2 = fmaxf(e2, ALPHA_F * e2); e3 = fmaxf(e3, ALPHA_F * e3);

    size_t E = (size_t)n_edges;
    float* o = out + (size_t)(4 * h) * E + e;
    o[0 * E] = __expf(e0) * s.x;
    o[1 * E] = __expf(e1) * s.y;
    o[2 * E] = __expf(e2) * s.z;
    o[3 * E] = __expf(e3) * s.w;
}

extern "C" void kernel_launch(void* const* d_in, const int* in_sizes, int n_in,
                              void* d_out, int out_size)
{
    const float* x   = (const float*)d_in[0];
    const int*   row = (const int*)  d_in[1];
    const int*   col = (const int*)  d_in[2];
    const float* aa  = (const float*)d_in[3];
    float* out = (float*)d_out;

    int n_nodes = in_sizes[0] / FDIM;   // 100000
    int n_edges = in_sizes[1];          // 1600000

    scores_kernel<<<592, 256>>>(x, aa, n_nodes);

    int nthreads = 2 * n_edges;
    sum_kernel<<<(nthreads + 255) / 256, 256>>>(row, col, n_edges);
    {
        int n2 = n_nodes * 2;
        inv_kernel<<<(n2 + 255) / 256, 256>>>(n2);
    }
    out_kernel<<<(nthreads + 255) / 256, 256>>>(row, col, out, n_edges);
}